// round 6
// baseline (speedup 1.0000x reference)
#include <cuda_runtime.h>
#include <cuda_bf16.h>
#include <cstdint>

// TopK(k=64) + sigmoid over rows of [16384, 4096] fp32. One CTA per row.
// Two full-row touches only: (1) load + prefilter (v >= 1.5 -> candidate
// buffer + 1024-bin hist over top-11 key bits; provably contains top-64 for
// N(0,1)); (2) output pass re-reading x (L1/L2-hot) with a float compare.
// Threshold resolved among ~20 bin candidates via warp0 all-pairs rank.
// Exact fallbacks (refinement loop re-reading x) cover arbitrary inputs.

constexpr int D    = 4096;
constexpr int T    = 256;
constexpr int KSEL = 64;
constexpr int NB   = 1024;          // histogram bins
constexpr int CCAP = 512;           // candidate buffer capacity
constexpr uint32_t T0   = 0xBFC00000u;  // f2k(1.5f), multiple of 2^21
constexpr uint32_t BIN0 = T0 >> 21;     // 1534

__device__ __forceinline__ uint32_t f2k(uint32_t u) {
    return u ^ ((uint32_t)((int)u >> 31) | 0x80000000u);  // monotonic key
}
__device__ __forceinline__ float k2f(uint32_t k) {
    uint32_t m = (uint32_t)((int)k >> 31);
    return __uint_as_float(k ^ (~m | 0x80000000u));
}
__device__ __forceinline__ float sigm(float f) {
    return __frcp_rn(1.0f + __expf(-f));
}

__global__ __launch_bounds__(T, 8)
void topk_sigmoid_kernel(const float* __restrict__ x,
                         float* __restrict__ out) {
    __shared__ __align__(16) int hist[NB];
    __shared__ __align__(16) uint32_t cand[CCAP];
    __shared__ __align__(16) int warpsum[8];
    __shared__ uint32_t s_bin;
    __shared__ int s_remk, s_neq, s_tot, s_n, s_n2;
    __shared__ uint32_t s_thr;
    __shared__ int s_allt, s_remk2;

    const int row  = blockIdx.x;
    const int tid  = threadIdx.x;
    const int lane = tid & 31;
    const int wrp  = tid >> 5;
    const float4* __restrict__ x4 =
        reinterpret_cast<const float4*>(x) + (size_t)row * (D / 4);

    // cand2 aliases hist (hist is dead once the last binsearch completes)
    uint32_t* cand2 = reinterpret_cast<uint32_t*>(hist);

    reinterpret_cast<int4*>(hist)[tid] = make_int4(0, 0, 0, 0);
    if (tid == 0) { s_n = 0; s_n2 = 0; }
    __syncthreads();

    // ---- touch 1: load + prefilter (candidates v >= 1.5) ----
    #pragma unroll
    for (int j = 0; j < 4; ++j) {
        float4 f = x4[tid + T * j];
        #pragma unroll
        for (int e = 0; e < 4; ++e) {
            float v = (e == 0) ? f.x : (e == 1) ? f.y : (e == 2) ? f.z : f.w;
            if (v >= 1.5f) {                 // ~274/4096 per row
                uint32_t kk = f2k(__float_as_uint(v));
                int t = atomicAdd(&s_n, 1);
                if (t < CCAP) cand[t] = kk;
                atomicAdd(&hist[(kk >> 21) - BIN0], 1);  // bins [0, 513]
            }
        }
    }
    __syncthreads();

    // ---- bin search over hist[NB]; tid owns 4 consecutive bins ----
    auto binsearch = [&](int remk) {
        int4 a = reinterpret_cast<const int4*>(hist)[tid];
        int h[4] = {a.x, a.y, a.z, a.w};
        int t[4];
        t[3] = h[3];
        #pragma unroll
        for (int j = 2; j >= 0; --j) t[j] = h[j] + t[j + 1];
        int tot = t[0];
        int s = tot;  // inclusive suffix over lanes >= mine
        #pragma unroll
        for (int o = 1; o < 32; o <<= 1) {
            int v = __shfl_down_sync(0xFFFFFFFFu, s, o);
            if (lane + o < 32) s += v;
        }
        if (lane == 0) warpsum[wrp] = s;
        __syncthreads();
        int above = 0, tot_all = 0;
        #pragma unroll
        for (int w = 0; w < 8; ++w) {
            int ws = warpsum[w];
            tot_all += ws;
            if (w > wrp) above += ws;
        }
        if (tid == 0) s_tot = tot_all;
        int G0 = above + (s - tot);
        #pragma unroll
        for (int j = 0; j < 4; ++j) {
            int G = G0 + t[j] - h[j];            // strictly above bin
            if (G < remk && G + h[j] >= remk) {  // exactly one bin matches
                s_bin  = (uint32_t)(tid * 4 + j);
                s_remk = remk - G;
                s_neq  = h[j];
            }
        }
    };

    binsearch(KSEL);
    __syncthreads();

    uint32_t prefix;
    int shift, remk, neq;
    bool fromx;
    if (s_tot >= KSEL) {
        prefix = BIN0 + s_bin;   // top 11 key bits of threshold
        shift  = 21;
        remk   = s_remk;
        neq    = s_neq;
        fromx  = (s_n > CCAP);   // candidate buffer overflowed (~never)
    } else {
        // exact fallback: select over the full key space
        prefix = 0; shift = 32; remk = KSEL; neq = D + 1; fromx = true;
    }

    // ---- rare refinement loop (re-reads x; L1/L2-hot) ----
    while (neq != remk && neq > 32 && shift > 0) {
        fromx = true;
        int w  = (shift < 9) ? shift : 9;
        int ns = shift - w;
        __syncthreads();
        reinterpret_cast<int4*>(hist)[tid] = make_int4(0, 0, 0, 0);
        __syncthreads();
        #pragma unroll
        for (int j = 0; j < 4; ++j) {
            float4 f = x4[tid + T * j];
            #pragma unroll
            for (int e = 0; e < 4; ++e) {
                float v = (e == 0) ? f.x : (e == 1) ? f.y : (e == 2) ? f.z : f.w;
                uint32_t kk = f2k(__float_as_uint(v));
                if (shift == 32 || (kk >> shift) == prefix)
                    atomicAdd(&hist[((kk >> ns) & ((1u << w) - 1u)) << (10 - w)], 1);
            }
        }
        __syncthreads();
        binsearch(remk);
        __syncthreads();
        prefix = (prefix << w) | (s_bin >> (10 - w));
        remk = s_remk;
        neq  = s_neq;
        shift = ns;
    }

    uint32_t thr;
    bool allt;
    int remk2 = remk;
    if (neq == remk) {
        thr = prefix << shift;   // whole remaining range included
        allt = true;
    } else if (shift == 0) {
        thr = prefix;            // exact thr; ties resolved by index
        allt = false;
    } else {
        // ---- gather the <=32 threshold-bin candidates into cand2 ----
        if (!fromx) {
            int n = s_n;  // <= CCAP here
            for (int i = tid; i < n; i += T) {
                uint32_t kk = cand[i];
                if ((kk >> 21) == prefix)
                    cand2[atomicAdd(&s_n2, 1)] = kk;
            }
        } else {
            #pragma unroll
            for (int j = 0; j < 4; ++j) {
                float4 f = x4[tid + T * j];
                #pragma unroll
                for (int e = 0; e < 4; ++e) {
                    float v = (e==0)?f.x:(e==1)?f.y:(e==2)?f.z:f.w;
                    uint32_t kk = f2k(__float_as_uint(v));
                    if ((kk >> shift) == prefix)
                        cand2[atomicAdd(&s_n2, 1)] = kk;
                }
            }
        }
        __syncthreads();
        // ---- warp0 all-pairs rank over <=32 keys (pipelined shfls) ----
        if (wrp == 0) {
            uint32_t mk = (lane < neq) ? cand2[lane] : 0u;
            int g = 0, e = 1;  // e includes self
            #pragma unroll
            for (int i = 1; i < 32; ++i) {
                uint32_t ok = __shfl_sync(0xFFFFFFFFu, mk, (lane + i) & 31);
                int ol = (lane + i) & 31;
                if (ol < neq) { g += (ok > mk); e += (ok == mk); }
            }
            if (lane < neq && g < remk && g + e >= remk) {
                s_thr   = mk;
                s_remk2 = remk - g;
                s_allt  = (e == remk - g);
            }
        }
        __syncthreads();
        thr   = s_thr;
        allt  = (s_allt != 0);
        remk2 = s_remk2;
    }

    // ---- touch 2: output (re-read x; rows are L1/L2-hot) ----
    float4* __restrict__ o4 =
        reinterpret_cast<float4*>(out) + (size_t)row * (D / 4);
    const float* __restrict__ xr = x + (size_t)row * D;

    if (thr > 0x80000000u) {
        // thr is a strictly-positive float: pure float-domain compare
        const float thrf = k2f(thr);
        #pragma unroll
        for (int j = 0; j < 4; ++j) {
            int v = tid + T * j;
            float4 f = x4[v];
            float4 r;
            #pragma unroll
            for (int e = 0; e < 4; ++e) {
                float vv = (e==0)?f.x:(e==1)?f.y:(e==2)?f.z:f.w;
                float o = 0.0f;
                if (vv >= thrf) {            // ~64/4096
                    bool inc = allt || (vv > thrf);
                    if (!inc) {              // exact index tie-break, ~never
                        int idx = 4 * v + e, rk = 0;
                        for (int q = 0; q < idx; ++q)
                            rk += (f2k(__float_as_uint(xr[q])) == thr);
                        inc = (rk < remk2);
                    }
                    if (inc) o = sigm(vv);
                }
                ((float*)&r)[e] = o;
            }
            o4[v] = r;
        }
    } else {
        // rare: thr <= +0 in key space — integer-domain compare (handles +-0)
        #pragma unroll
        for (int j = 0; j < 4; ++j) {
            int v = tid + T * j;
            float4 f = x4[v];
            float4 r;
            #pragma unroll
            for (int e = 0; e < 4; ++e) {
                float vv = (e==0)?f.x:(e==1)?f.y:(e==2)?f.z:f.w;
                uint32_t kk = f2k(__float_as_uint(vv));
                float o = 0.0f;
                if (kk >= thr) {
                    bool inc = allt || (kk > thr);
                    if (!inc) {
                        int idx = 4 * v + e, rk = 0;
                        for (int q = 0; q < idx; ++q)
                            rk += (f2k(__float_as_uint(xr[q])) == thr);
                        inc = (rk < remk2);
                    }
                    if (inc) o = sigm(vv);
                }
                ((float*)&r)[e] = o;
            }
            o4[v] = r;
        }
    }
}

extern "C" void kernel_launch(void* const* d_in, const int* in_sizes, int n_in,
                              void* d_out, int out_size) {
    const float* x = (const float*)d_in[0];
    float* out = (float*)d_out;
    int rows = in_sizes[0] / D;
    topk_sigmoid_kernel<<<rows, T>>>(x, out);
}

// round 7
// speedup vs baseline: 1.1269x; 1.1269x over previous
#include <cuda_runtime.h>
#include <cuda_bf16.h>
#include <cstdint>

// TopK(k=64) + sigmoid over rows of [16384, 4096] fp32.
// One CTA (512 threads) per row; 8 floats/thread live in REGISTERS.
// Exactly one global read + one global write of the row.
// Selection: predicated 1024-bin hist over top-11 key bits (keys >= f2k(1.5),
// provably contains top-64 for N(0,1) rows), warp0 two-sweep bin search,
// register compaction of the ~20 threshold-bin keys, warp0 all-pairs rank.
// Exact fallbacks (full hist + refinement over register keys) cover any input.

constexpr int D    = 4096;
constexpr int T    = 512;
constexpr int EPT  = D / T;          // 8
constexpr int KSEL = 64;
constexpr int NB   = 1024;
constexpr uint32_t T0   = 0xBFC00000u;   // f2k(1.5f), multiple of 2^21
constexpr uint32_t BIN0 = T0 >> 21;      // 1534

__device__ __forceinline__ uint32_t f2k(uint32_t u) {
    return u ^ ((uint32_t)((int)u >> 31) | 0x80000000u);  // monotonic key
}
__device__ __forceinline__ float k2f(uint32_t k) {
    uint32_t m = (uint32_t)((int)k >> 31);
    return __uint_as_float(k ^ (~m | 0x80000000u));
}
__device__ __forceinline__ float sigm(float f) {
    return __frcp_rn(1.0f + __expf(-f));
}

__global__ __launch_bounds__(T, 3)
void topk_sigmoid_kernel(const float* __restrict__ x,
                         float* __restrict__ out) {
    __shared__ __align__(16) int hist[NB];
    __shared__ uint32_t cand[32];
    __shared__ uint32_t s_bin;
    __shared__ int s_remk, s_neq, s_tot, s_n2;
    __shared__ uint32_t s_thr;
    __shared__ int s_allt, s_remk2;

    const int row  = blockIdx.x;
    const int tid  = threadIdx.x;
    const int lane = tid & 31;
    const int wrp  = tid >> 5;
    const float4* __restrict__ x4 =
        reinterpret_cast<const float4*>(x) + (size_t)row * (D / 4);

    reinterpret_cast<int2*>(hist)[tid] = make_int2(0, 0);
    if (tid == 0) s_n2 = 0;
    __syncthreads();

    // ---- the ONLY global read: 8 floats into registers ----
    float4 fa = x4[tid];
    float4 fb = x4[tid + T];
    float v[EPT] = {fa.x, fa.y, fa.z, fa.w, fb.x, fb.y, fb.z, fb.w};

    // ---- predicated histogram: only ~274/4096 candidates per row ----
    #pragma unroll
    for (int e = 0; e < EPT; ++e) {
        if (v[e] >= 1.5f) {
            uint32_t kk = f2k(__float_as_uint(v[e]));
            atomicAdd(&hist[(kk >> 21) - BIN0], 1);  // bins [0, 513]
        }
    }
    __syncthreads();

    // ---- warp0-only two-sweep bin search over hist[NB] ----
    // lane owns 32 consecutive bins [lane*32, lane*32+32)
    auto binsearch = [&](int remk) {
        if (wrp == 0) {
            int tot = 0;
            #pragma unroll
            for (int i = 0; i < 8; ++i) {
                int4 q = reinterpret_cast<const int4*>(hist)[lane * 8 + i];
                tot += q.x + q.y + q.z + q.w;
            }
            int s = tot;  // inclusive suffix over lanes >= mine
            #pragma unroll
            for (int o = 1; o < 32; o <<= 1) {
                int q = __shfl_down_sync(0xFFFFFFFFu, s, o);
                if (lane + o < 32) s += q;
            }
            if (lane == 0) s_tot = s;
            int cum = s - tot;  // bins in higher lanes (strictly above mine)
            // descending sweep through my 32 bins
            #pragma unroll
            for (int i = 7; i >= 0; --i) {
                int4 q = reinterpret_cast<const int4*>(hist)[lane * 8 + i];
                int hh[4] = {q.x, q.y, q.z, q.w};
                #pragma unroll
                for (int j = 3; j >= 0; --j) {
                    if (cum < remk && cum + hh[j] >= remk) {  // unique hit
                        s_bin  = (uint32_t)(lane * 32 + i * 4 + j);
                        s_remk = remk - cum;
                        s_neq  = hh[j];
                    }
                    cum += hh[j];
                }
            }
        }
    };

    binsearch(KSEL);
    __syncthreads();

    uint32_t prefix;
    int shift, remk, neq;
    if (s_tot >= KSEL) {
        prefix = BIN0 + s_bin;   // threshold's top 11 key bits
        shift  = 21;
        remk   = s_remk;
        neq    = s_neq;
    } else {
        // exact fallback (~never for N(0,1)): full top-10-bit histogram
        __syncthreads();
        reinterpret_cast<int2*>(hist)[tid] = make_int2(0, 0);
        __syncthreads();
        #pragma unroll
        for (int e = 0; e < EPT; ++e)
            atomicAdd(&hist[f2k(__float_as_uint(v[e])) >> 22], 1);
        __syncthreads();
        binsearch(KSEL);
        __syncthreads();
        prefix = s_bin;
        shift  = 22;
        remk   = s_remk;
        neq    = s_neq;
    }

    // ---- rare refinement levels over REGISTER keys ----
    while (neq != remk && neq > 32 && shift > 0) {
        int w  = (shift < 10) ? shift : 10;
        int ns = shift - w;
        __syncthreads();
        reinterpret_cast<int2*>(hist)[tid] = make_int2(0, 0);
        __syncthreads();
        #pragma unroll
        for (int e = 0; e < EPT; ++e) {
            uint32_t kk = f2k(__float_as_uint(v[e]));
            if ((kk >> shift) == prefix)
                atomicAdd(&hist[(kk >> ns) & ((1u << w) - 1u)], 1);
        }
        __syncthreads();
        binsearch(remk);
        __syncthreads();
        prefix = (prefix << w) | s_bin;
        remk = s_remk;
        neq  = s_neq;
        shift = ns;
    }

    uint32_t thr;
    bool allt;
    int remk2 = remk;
    if (neq == remk) {
        thr = prefix << shift;   // whole remaining range included
        allt = true;
    } else if (shift == 0) {
        thr = prefix;            // exact thr; remaining ties by index (rare)
        allt = false;
    } else {
        // ---- compact the <=32 threshold-bin keys from registers ----
        #pragma unroll
        for (int e = 0; e < EPT; ++e) {
            uint32_t kk = f2k(__float_as_uint(v[e]));
            if ((kk >> shift) == prefix)
                cand[atomicAdd(&s_n2, 1)] = kk;
        }
        __syncthreads();
        // ---- warp0 all-pairs rank over <=32 keys ----
        if (wrp == 0) {
            uint32_t mk = (lane < neq) ? cand[lane] : 0u;
            int g = 0, eq = 1;  // eq includes self
            #pragma unroll
            for (int i = 1; i < 32; ++i) {
                uint32_t ok = __shfl_sync(0xFFFFFFFFu, mk, (lane + i) & 31);
                int ol = (lane + i) & 31;
                if (ol < neq) { g += (ok > mk); eq += (ok == mk); }
            }
            if (lane < neq && g < remk && g + eq >= remk) {
                s_thr   = mk;
                s_remk2 = remk - g;
                s_allt  = (eq == remk - g);
            }
        }
        __syncthreads();
        thr   = s_thr;
        allt  = (s_allt != 0);
        remk2 = s_remk2;
    }

    // ---- the ONLY global write: output from registers ----
    float4* __restrict__ o4 =
        reinterpret_cast<float4*>(out) + (size_t)row * (D / 4);
    float r[EPT];

    if (thr > 0x80000000u) {
        // threshold is a strictly-positive float: pure float compares
        const float thrf = k2f(thr);
        #pragma unroll
        for (int e = 0; e < EPT; ++e) {
            float o = 0.0f;
            if (v[e] >= thrf) {                  // ~64/4096
                bool inc = allt || (v[e] > thrf);
                if (!inc) {                      // exact index tie-break, rare
                    int idx = 4 * (tid + T * (e >> 2)) + (e & 3);
                    const float* xr = x + (size_t)row * D;
                    int rk = 0;
                    for (int q = 0; q < idx; ++q)
                        rk += (f2k(__float_as_uint(xr[q])) == thr);
                    inc = (rk < remk2);
                }
                if (inc) o = sigm(v[e]);
            }
            r[e] = o;
        }
    } else {
        // rare: thr at/below +0 in key space — integer-domain compare
        #pragma unroll
        for (int e = 0; e < EPT; ++e) {
            uint32_t kk = f2k(__float_as_uint(v[e]));
            float o = 0.0f;
            if (kk >= thr) {
                bool inc = allt || (kk > thr);
                if (!inc) {
                    int idx = 4 * (tid + T * (e >> 2)) + (e & 3);
                    const float* xr = x + (size_t)row * D;
                    int rk = 0;
                    for (int q = 0; q < idx; ++q)
                        rk += (f2k(__float_as_uint(xr[q])) == thr);
                    inc = (rk < remk2);
                }
                if (inc) o = sigm(v[e]);
            }
            r[e] = o;
        }
    }

    o4[tid]     = make_float4(r[0], r[1], r[2], r[3]);
    o4[tid + T] = make_float4(r[4], r[5], r[6], r[7]);
}

extern "C" void kernel_launch(void* const* d_in, const int* in_sizes, int n_in,
                              void* d_out, int out_size) {
    const float* x = (const float*)d_in[0];
    float* out = (float*)d_out;
    int rows = in_sizes[0] / D;
    topk_sigmoid_kernel<<<rows, T>>>(x, out);
}

// round 8
// speedup vs baseline: 1.6275x; 1.4443x over previous
#include <cuda_runtime.h>
#include <cuda_bf16.h>
#include <cstdint>

// TopK(k=64) + sigmoid over rows of [16384, 4096] fp32.
// One 256-thread CTA per row (8 CTAs/SM for stall overlap), keys in shared.
// Selection: predicated 1024-bin hist over top-11 key bits (keys >= f2k(1.5),
// provably contains top-64 for N(0,1) rows; exact fallback otherwise),
// warp0-only bin search, compaction of ~20 threshold-bin keys from shared,
// warp0 all-pairs rank for the exact threshold. 5 barriers on the hot path.

constexpr int D    = 4096;
constexpr int T    = 256;
constexpr int KSEL = 64;
constexpr int NB   = 1024;
constexpr uint32_t T0   = 0xBFC00000u;   // f2k(1.5f), multiple of 2^21
constexpr uint32_t BIN0 = T0 >> 21;      // 1534

__device__ __forceinline__ uint32_t f2k(uint32_t u) {
    return u ^ ((uint32_t)((int)u >> 31) | 0x80000000u);  // monotonic key
}
__device__ __forceinline__ float k2f(uint32_t k) {
    uint32_t m = (uint32_t)((int)k >> 31);
    return __uint_as_float(k ^ (~m | 0x80000000u));
}
__device__ __forceinline__ float sigm(float f) {
    return __frcp_rn(1.0f + __expf(-f));
}

__global__ __launch_bounds__(T, 8)
void topk_sigmoid_kernel(const float* __restrict__ x,
                         float* __restrict__ out) {
    __shared__ __align__(16) uint32_t skey[D];
    __shared__ __align__(16) int hist[NB];
    __shared__ uint32_t cand[32];
    __shared__ uint32_t s_bin;
    __shared__ int s_remk, s_neq, s_tot, s_n2;
    __shared__ uint32_t s_thr;
    __shared__ int s_allt, s_remk2;

    const int row  = blockIdx.x;
    const int tid  = threadIdx.x;
    const int lane = tid & 31;
    const int wrp  = tid >> 5;
    const uint4* __restrict__ x4 =
        reinterpret_cast<const uint4*>(x) + (size_t)row * (D / 4);

    reinterpret_cast<int4*>(hist)[tid] = make_int4(0, 0, 0, 0);  // 4 bins/thr
    if (tid == 0) s_n2 = 0;
    __syncthreads();

    // ---- load + convert + stage keys + predicated histogram ----
    // Only keys >= f2k(1.5) (~274/row) hit the hist; they spread over ~500
    // of 514 live bins -> negligible atomic contention, no aggregation needed.
    #pragma unroll
    for (int j = 0; j < 4; ++j) {
        int v = tid + T * j;
        uint4 u = x4[v];
        uint4 kk;
        kk.x = f2k(u.x); kk.y = f2k(u.y); kk.z = f2k(u.z); kk.w = f2k(u.w);
        reinterpret_cast<uint4*>(skey)[v] = kk;
        if (kk.x >= T0) atomicAdd(&hist[(kk.x >> 21) - BIN0], 1);
        if (kk.y >= T0) atomicAdd(&hist[(kk.y >> 21) - BIN0], 1);
        if (kk.z >= T0) atomicAdd(&hist[(kk.z >> 21) - BIN0], 1);
        if (kk.w >= T0) atomicAdd(&hist[(kk.w >> 21) - BIN0], 1);
    }
    __syncthreads();

    // ---- warp0-only two-sweep bin search; lane owns 32 consecutive bins ----
    auto binsearch = [&](int remk) {
        if (wrp == 0) {
            int tot = 0;
            #pragma unroll
            for (int i = 0; i < 8; ++i) {
                int4 q = reinterpret_cast<const int4*>(hist)[lane * 8 + i];
                tot += q.x + q.y + q.z + q.w;
            }
            int s = tot;  // inclusive suffix over lanes >= mine
            #pragma unroll
            for (int o = 1; o < 32; o <<= 1) {
                int q = __shfl_down_sync(0xFFFFFFFFu, s, o);
                if (lane + o < 32) s += q;
            }
            if (lane == 0) s_tot = s;
            int cum = s - tot;  // count in bins strictly above my 32
            #pragma unroll
            for (int i = 7; i >= 0; --i) {
                int4 q = reinterpret_cast<const int4*>(hist)[lane * 8 + i];
                int hh[4] = {q.x, q.y, q.z, q.w};
                #pragma unroll
                for (int j = 3; j >= 0; --j) {
                    if (cum < remk && cum + hh[j] >= remk) {  // unique hit
                        s_bin  = (uint32_t)(lane * 32 + i * 4 + j);
                        s_remk = remk - cum;
                        s_neq  = hh[j];
                    }
                    cum += hh[j];
                }
            }
        }
    };

    binsearch(KSEL);
    __syncthreads();

    uint32_t prefix;
    int shift, remk, neq;
    if (s_tot >= KSEL) {
        prefix = BIN0 + s_bin;   // threshold's top 11 key bits
        shift  = 21;
        remk   = s_remk;
        neq    = s_neq;
    } else {
        // exact fallback (~never for N(0,1)): full top-10-bit histogram
        __syncthreads();
        reinterpret_cast<int4*>(hist)[tid] = make_int4(0, 0, 0, 0);
        __syncthreads();
        #pragma unroll
        for (int j = 0; j < 4; ++j) {
            uint4 kk = reinterpret_cast<const uint4*>(skey)[tid + T * j];
            atomicAdd(&hist[kk.x >> 22], 1);
            atomicAdd(&hist[kk.y >> 22], 1);
            atomicAdd(&hist[kk.z >> 22], 1);
            atomicAdd(&hist[kk.w >> 22], 1);
        }
        __syncthreads();
        binsearch(KSEL);
        __syncthreads();
        prefix = s_bin;
        shift  = 22;
        remk   = s_remk;
        neq    = s_neq;
    }

    // ---- rare refinement levels (massive ties) over staged keys ----
    while (neq != remk && neq > 32 && shift > 0) {
        int w  = (shift < 10) ? shift : 10;
        int ns = shift - w;
        __syncthreads();
        reinterpret_cast<int4*>(hist)[tid] = make_int4(0, 0, 0, 0);
        __syncthreads();
        #pragma unroll
        for (int j = 0; j < 4; ++j) {
            uint4 k4 = reinterpret_cast<const uint4*>(skey)[tid + T * j];
            #pragma unroll
            for (int e = 0; e < 4; ++e) {
                uint32_t kk = (e == 0) ? k4.x : (e == 1) ? k4.y
                            : (e == 2) ? k4.z : k4.w;
                if ((kk >> shift) == prefix)
                    atomicAdd(&hist[(kk >> ns) & ((1u << w) - 1u)], 1);
            }
        }
        __syncthreads();
        binsearch(remk);
        __syncthreads();
        prefix = (prefix << w) | s_bin;
        remk = s_remk;
        neq  = s_neq;
        shift = ns;
    }

    uint32_t thr;
    bool allt;
    int remk2 = remk;
    if (neq == remk) {
        thr = prefix << shift;   // whole remaining range included
        allt = true;
    } else if (shift == 0) {
        thr = prefix;            // exact thr; residual ties by index (rare)
        allt = false;
    } else {
        // ---- compact the <=32 threshold-bin keys from shared ----
        #pragma unroll
        for (int j = 0; j < 4; ++j) {
            uint4 k4 = reinterpret_cast<const uint4*>(skey)[tid + T * j];
            #pragma unroll
            for (int e = 0; e < 4; ++e) {
                uint32_t kk = (e == 0) ? k4.x : (e == 1) ? k4.y
                            : (e == 2) ? k4.z : k4.w;
                if ((kk >> shift) == prefix) {
                    int t = atomicAdd(&s_n2, 1);
                    if (t < 32) cand[t] = kk;
                }
            }
        }
        __syncthreads();
        // ---- warp0 all-pairs rank over <=32 keys ----
        if (wrp == 0) {
            uint32_t mk = (lane < neq) ? cand[lane] : 0u;
            int g = 0, eq = 1;  // eq includes self
            #pragma unroll
            for (int i = 1; i < 32; ++i) {
                uint32_t ok = __shfl_sync(0xFFFFFFFFu, mk, (lane + i) & 31);
                int ol = (lane + i) & 31;
                if (ol < neq) { g += (ok > mk); eq += (ok == mk); }
            }
            if (lane < neq && g < remk && g + eq >= remk) {
                s_thr   = mk;
                s_remk2 = remk - g;
                s_allt  = (eq == remk - g);
            }
        }
        __syncthreads();
        thr   = s_thr;
        allt  = (s_allt != 0);
        remk2 = s_remk2;
    }

    // ---- output: sigmoid for selected, 0 otherwise (128-bit coalesced) ----
    float4* __restrict__ o4 =
        reinterpret_cast<float4*>(out) + (size_t)row * (D / 4);
    #pragma unroll
    for (int j = 0; j < 4; ++j) {
        int v = tid + T * j;
        uint4 k4 = reinterpret_cast<const uint4*>(skey)[v];
        float4 r;
        #pragma unroll
        for (int e = 0; e < 4; ++e) {
            uint32_t kk = (e == 0) ? k4.x : (e == 1) ? k4.y
                        : (e == 2) ? k4.z : k4.w;
            float o = 0.0f;
            if (kk >= thr) {                 // ~64/4096
                bool inc = allt || (kk > thr);
                if (!inc) {                  // exact index tie-break, ~never
                    int idx = 4 * v + e, rk = 0;
                    for (int q = 0; q < idx; ++q) rk += (skey[q] == thr);
                    inc = (rk < remk2);
                }
                if (inc) o = sigm(k2f(kk));
            }
            ((float*)&r)[e] = o;
        }
        o4[v] = r;
    }
}

extern "C" void kernel_launch(void* const* d_in, const int* in_sizes, int n_in,
                              void* d_out, int out_size) {
    const float* x = (const float*)d_in[0];
    float* out = (float*)d_out;
    int rows = in_sizes[0] / D;
    topk_sigmoid_kernel<<<rows, T>>>(x, out);
}

// round 9
// speedup vs baseline: 1.9860x; 1.2202x over previous
#include <cuda_runtime.h>
#include <cuda_bf16.h>
#include <cstdint>

// TopK(k=64) + sigmoid over rows of [16384, 4096] fp32. One 256-thread CTA/row.
// Load loop: LDG row, STG zeros to out, push candidates (v >= 1.5, ~274/row,
// provably superset of top-64 for N(0,1)) into per-warp smem buffers + a
// 1024-bin VALUE histogram (bin = (v-1.5)*256 -> ~2/bin, fully spread atomics,
// threshold bin ~1 member). Warp0 bin search + rank-32 give the exact
// threshold; winners scatter-overwrite their zeros. Any anomaly (tail < 64,
// buffer overflow, bin > 32 ties) -> block-uniform exact radix slow path.

constexpr int D    = 4096;
constexpr int T    = 256;
constexpr int KSEL = 64;
constexpr int NB   = 1024;   // value bins over [1.5, 5.5], clamp above
constexpr int NW   = 8;      // warps per CTA
constexpr int WCAP = 64;     // per-warp candidate capacity

__device__ __forceinline__ uint32_t f2k(uint32_t u) {
    return u ^ ((uint32_t)((int)u >> 31) | 0x80000000u);  // monotonic key
}
__device__ __forceinline__ float k2f(uint32_t k) {
    uint32_t m = (uint32_t)((int)k >> 31);
    return __uint_as_float(k ^ (~m | 0x80000000u));
}
__device__ __forceinline__ float sigm(float f) {
    return __frcp_rn(1.0f + __expf(-f));
}
__device__ __forceinline__ int vbin(float v) {
    // monotone non-decreasing value->bin map; v>=1.5 -> bin>=0; +inf -> NB-1
    return min(__float2int_rd((v - 1.5f) * 256.0f), NB - 1);
}

__global__ __launch_bounds__(T, 8)
void topk_sigmoid_kernel(const float* __restrict__ x,
                         float* __restrict__ out) {
    __shared__ __align__(16) int hist[NB];
    __shared__ __align__(16) uint32_t cbk[NW * WCAP];  // candidate keys
    __shared__ __align__(16) uint32_t cbm[NW * WCAP];  // (bin<<12) | idx
    __shared__ int s_cnt[NW];
    __shared__ uint32_t cand[32];
    __shared__ uint32_t s_bin, s_thr;
    __shared__ int s_remk, s_neq, s_tot, s_n2, s_ovf, s_allt, s_remk2;

    const int row  = blockIdx.x;
    const int tid  = threadIdx.x;
    const int lane = tid & 31;
    const int wrp  = tid >> 5;
    const uint4* __restrict__ x4 =
        reinterpret_cast<const uint4*>(x) + (size_t)row * (D / 4);
    float4* __restrict__ o4 =
        reinterpret_cast<float4*>(out) + (size_t)row * (D / 4);

    reinterpret_cast<int4*>(hist)[tid] = make_int4(0, 0, 0, 0);  // 4 bins/thr
    if (tid < NW) s_cnt[tid] = 0;
    if (tid == 0) { s_n2 = 0; s_ovf = 0; s_tot = 0; s_neq = 1 << 30; }
    __syncthreads();

    // ---- load + zero-out + candidate push (the only full-row touch) ----
    #pragma unroll
    for (int j = 0; j < 4; ++j) {
        int v4 = tid + T * j;
        uint4 u = x4[v4];
        o4[v4] = make_float4(0.f, 0.f, 0.f, 0.f);
        #pragma unroll
        for (int e = 0; e < 4; ++e) {
            uint32_t ub = (e == 0) ? u.x : (e == 1) ? u.y : (e == 2) ? u.z : u.w;
            float vv = __uint_as_float(ub);
            if (vv >= 1.5f) {                       // ~274/4096 per row
                int b = vbin(vv);
                atomicAdd(&hist[b], 1);             // spread: ~2 keys/bin
                int p = atomicAdd(&s_cnt[wrp], 1);  // per-warp ticket
                if (p < WCAP) {
                    cbk[wrp * WCAP + p] = f2k(ub);
                    cbm[wrp * WCAP + p] = ((uint32_t)b << 12) | (uint32_t)(4 * v4 + e);
                }
            }
        }
    }
    __syncthreads();

    // ---- warp0-only bin search; lane owns 32 consecutive bins ----
    auto binsearch = [&](int remk) {
        if (wrp == 0) {
            int tot = 0;
            #pragma unroll
            for (int i = 0; i < 8; ++i) {
                int4 q = reinterpret_cast<const int4*>(hist)[lane * 8 + i];
                tot += q.x + q.y + q.z + q.w;
            }
            int s = tot;  // inclusive suffix over lanes >= mine
            #pragma unroll
            for (int o = 1; o < 32; o <<= 1) {
                int q = __shfl_down_sync(0xFFFFFFFFu, s, o);
                if (lane + o < 32) s += q;
            }
            if (lane == 0) s_tot = s;
            int cum = s - tot;  // count in bins strictly above my 32
            #pragma unroll
            for (int i = 7; i >= 0; --i) {
                int4 q = reinterpret_cast<const int4*>(hist)[lane * 8 + i];
                int hh[4] = {q.x, q.y, q.z, q.w};
                #pragma unroll
                for (int j = 3; j >= 0; --j) {
                    if (cum < remk && cum + hh[j] >= remk) {  // unique hit
                        s_bin  = (uint32_t)(lane * 32 + i * 4 + j);
                        s_remk = remk - cum;
                        s_neq  = hh[j];
                    }
                    cum += hh[j];
                }
            }
        }
    };

    if (tid < NW && s_cnt[tid] > WCAP) s_ovf = 1;
    binsearch(KSEL);
    __syncthreads();

    const bool fast = (s_ovf == 0) && (s_tot >= KSEL) && (s_neq <= 32);

    if (fast) {
        const uint32_t bsel = s_bin;
        const int remk = s_remk, neq = s_neq;

        // ---- compact the <=32 threshold-bin keys (scan 512 slots) ----
        #pragma unroll
        for (int i = 0; i < 2; ++i) {
            int s = tid + T * i;
            int w = s >> 6;
            if ((s & 63) < min(s_cnt[w], WCAP) && (cbm[s] >> 12) == bsel) {
                int t = atomicAdd(&s_n2, 1);
                if (t < 32) cand[t] = cbk[s];
            }
        }
        __syncthreads();

        // ---- warp0 all-pairs rank over <=32 keys -> exact threshold ----
        if (wrp == 0) {
            uint32_t mk = (lane < neq) ? cand[lane] : 0u;
            int g = 0, eq = 1;  // eq includes self
            #pragma unroll
            for (int i = 1; i < 32; ++i) {
                uint32_t ok = __shfl_sync(0xFFFFFFFFu, mk, (lane + i) & 31);
                int ol = (lane + i) & 31;
                if (ol < neq) { g += (ok > mk); eq += (ok == mk); }
            }
            if (lane < neq && g < remk && g + eq >= remk) {
                s_thr   = mk;
                s_remk2 = remk - g;
                s_allt  = (eq == remk - g);
            }
        }
        __syncthreads();
        const uint32_t thr = s_thr;
        const bool allt = (s_allt != 0);
        const int remk2 = s_remk2;

        // ---- scatter winners over the pre-written zeros ----
        #pragma unroll
        for (int i = 0; i < 2; ++i) {
            int s = tid + T * i;
            int w = s >> 6;
            if ((s & 63) < min(s_cnt[w], WCAP)) {
                uint32_t kk = cbk[s];
                if (kk >= thr) {
                    bool inc = allt || (kk > thr);
                    if (!inc) {  // tie at thr: lowest indices first (~never)
                        uint32_t myi = cbm[s] & 0xFFFu;
                        int rk = 0;
                        for (int q = 0; q < NW * WCAP; ++q) {
                            int qw = q >> 6;
                            if ((q & 63) < min(s_cnt[qw], WCAP) &&
                                cbk[q] == thr && (cbm[q] & 0xFFFu) < myi)
                                rk++;
                        }
                        inc = (rk < remk2);
                    }
                    if (inc)
                        out[(size_t)row * D + (cbm[s] & 0xFFFu)] = sigm(k2f(kk));
                }
            }
        }
        return;
    }

    // ---- slow exact path (block-uniform, ~never): key-radix over global x ----
    {
        uint32_t prefix = 0;
        int shift = 32, remk = KSEL, neq = 0;
        while (true) {
            int w  = (shift < 9) ? shift : 9;
            int ns = shift - w;
            __syncthreads();
            reinterpret_cast<int4*>(hist)[tid] = make_int4(0, 0, 0, 0);
            __syncthreads();
            #pragma unroll
            for (int j = 0; j < 4; ++j) {
                uint4 u = x4[tid + T * j];
                #pragma unroll
                for (int e = 0; e < 4; ++e) {
                    uint32_t kk = f2k((e == 0) ? u.x : (e == 1) ? u.y
                                     : (e == 2) ? u.z : u.w);
                    bool m = (shift == 32) || ((kk >> shift) == prefix);
                    if (m) atomicAdd(&hist[(kk >> ns) & ((1u << w) - 1u)], 1);
                }
            }
            __syncthreads();
            binsearch(remk);
            __syncthreads();
            prefix = (prefix << w) | s_bin;
            remk = s_remk;
            neq  = s_neq;
            shift = ns;
            if (neq == remk || shift == 0) break;
        }
        uint32_t thr;
        bool allt;
        int remk2 = remk;
        if (neq == remk) { thr = prefix << shift; allt = true; }
        else             { thr = prefix;          allt = false; }

        #pragma unroll
        for (int j = 0; j < 4; ++j) {
            int v4 = tid + T * j;
            uint4 u = x4[v4];
            float4 r;
            #pragma unroll
            for (int e = 0; e < 4; ++e) {
                uint32_t ub = (e == 0) ? u.x : (e == 1) ? u.y
                            : (e == 2) ? u.z : u.w;
                uint32_t kk = f2k(ub);
                float o = 0.f;
                if (kk >= thr) {
                    bool inc = allt || (kk > thr);
                    if (!inc) {  // index tie-break via global scan (exact)
                        int idx = 4 * v4 + e, rk = 0;
                        const float* xr = x + (size_t)row * D;
                        for (int q = 0; q < idx; ++q)
                            rk += (f2k(__float_as_uint(xr[q])) == thr);
                        inc = (rk < remk2);
                    }
                    if (inc) o = sigm(k2f(kk));
                }
                ((float*)&r)[e] = o;
            }
            o4[v4] = r;
        }
    }
}

extern "C" void kernel_launch(void* const* d_in, const int* in_sizes, int n_in,
                              void* d_out, int out_size) {
    const float* x = (const float*)d_in[0];
    float* out = (float*)d_out;
    int rows = in_sizes[0] / D;
    topk_sigmoid_kernel<<<rows, T>>>(x, out);
}

// round 10
// speedup vs baseline: 2.3811x; 1.1990x over previous
#include <cuda_runtime.h>
#include <cuda_bf16.h>
#include <cstdint>

// TopK(k=64) + sigmoid over rows of [16384, 4096] fp32. One 256-thread CTA/row.
// Load loop: LDG row, STG zeros, push candidates (v >= 1.5, ~274/row, provably
// superset of top-64 for N(0,1)) into per-warp smem buffers with BALLOT tickets
// (zero atomics) + a 256-bin VALUE histogram (bin=(v-1.5)*128, spread atomics).
// Warp0 bin search (256 bins) + all-pairs rank-32 give the exact threshold;
// winners scatter-overwrite their zeros. Anomalies (tail<64, overflow, >32
// ties in a bin) -> block-uniform exact radix slow path over global x.

constexpr int D    = 4096;
constexpr int T    = 256;
constexpr int KSEL = 64;
constexpr int NB   = 256;    // value bins over [1.5, 3.5], clamp above
constexpr int NW   = 8;      // warps per CTA
constexpr int WCAP = 64;     // per-warp candidate capacity

__device__ __forceinline__ uint32_t f2k(uint32_t u) {
    return u ^ ((uint32_t)((int)u >> 31) | 0x80000000u);  // monotonic key
}
__device__ __forceinline__ float k2f(uint32_t k) {
    uint32_t m = (uint32_t)((int)k >> 31);
    return __uint_as_float(k ^ (~m | 0x80000000u));
}
__device__ __forceinline__ float sigm(float f) {
    return __frcp_rn(1.0f + __expf(-f));
}
__device__ __forceinline__ int vbin(float v) {
    // monotone; v>=1.5 -> bin>=0; clamp to NB-1 (FFMA + F2I + IMNMX)
    return min(__float2int_rd(__fmaf_rz(v, 128.0f, -192.0f)), NB - 1);
}

__global__ __launch_bounds__(T, 8)
void topk_sigmoid_kernel(const float* __restrict__ x,
                         float* __restrict__ out) {
    __shared__ __align__(16) int hist[NB];
    __shared__ __align__(16) uint32_t cbk[NW * WCAP];  // candidate keys
    __shared__ __align__(16) uint32_t cbm[NW * WCAP];  // (bin<<12) | idx
    __shared__ int s_cnt[NW];
    __shared__ uint32_t cand[32];
    __shared__ uint32_t s_bin, s_thr;
    __shared__ int s_remk, s_neq, s_tot, s_n2, s_allt, s_remk2;

    const int row  = blockIdx.x;
    const int tid  = threadIdx.x;
    const int lane = tid & 31;
    const int wrp  = tid >> 5;
    const uint4* __restrict__ x4 =
        reinterpret_cast<const uint4*>(x) + (size_t)row * (D / 4);
    float4* __restrict__ o4 =
        reinterpret_cast<float4*>(out) + (size_t)row * (D / 4);

    hist[tid] = 0;                       // NB == T
    if (tid == 0) { s_n2 = 0; s_tot = 0; s_neq = 1 << 30; }
    __syncthreads();

    // ---- load + zero-out + ballot-ticket candidate push ----
    uint32_t wbase = 0;                  // per-warp slot cursor (register)
    const uint32_t ltmask = (1u << lane) - 1u;
    #pragma unroll
    for (int j = 0; j < 4; ++j) {
        int v4 = tid + T * j;
        uint4 u = x4[v4];
        o4[v4] = make_float4(0.f, 0.f, 0.f, 0.f);
        #pragma unroll
        for (int e = 0; e < 4; ++e) {
            uint32_t ub = (e == 0) ? u.x : (e == 1) ? u.y : (e == 2) ? u.z : u.w;
            float vv = __uint_as_float(ub);
            bool c = (vv >= 1.5f);                   // ~274/4096 per row
            unsigned act = __ballot_sync(0xFFFFFFFFu, c);
            if (c) {
                int b = vbin(vv);
                atomicAdd(&hist[b], 1);              // spread: ~2 keys/bin
                uint32_t slot = wbase + __popc(act & ltmask);
                if (slot < WCAP) {
                    cbk[wrp * WCAP + slot] = f2k(ub);
                    cbm[wrp * WCAP + slot] =
                        ((uint32_t)b << 12) | (uint32_t)(4 * v4 + e);
                }
            }
            wbase += __popc(act);
        }
    }
    if (lane == 0) s_cnt[wrp] = (int)wbase;
    __syncthreads();

    // ---- warp0-only bin search over hist[256]; lane owns 8 bins ----
    auto binsearch = [&](int remk) {
        if (wrp == 0) {
            int4 qa = reinterpret_cast<const int4*>(hist)[lane * 2];
            int4 qb = reinterpret_cast<const int4*>(hist)[lane * 2 + 1];
            int tot = qa.x + qa.y + qa.z + qa.w + qb.x + qb.y + qb.z + qb.w;
            int s = tot;  // inclusive suffix over lanes >= mine
            #pragma unroll
            for (int o = 1; o < 32; o <<= 1) {
                int q = __shfl_down_sync(0xFFFFFFFFu, s, o);
                if (lane + o < 32) s += q;
            }
            if (lane == 0) s_tot = s;
            int cum = s - tot;  // count in bins strictly above my 8
            int hh[8] = {qa.x, qa.y, qa.z, qa.w, qb.x, qb.y, qb.z, qb.w};
            #pragma unroll
            for (int j = 7; j >= 0; --j) {
                if (cum < remk && cum + hh[j] >= remk) {  // unique hit
                    s_bin  = (uint32_t)(lane * 8 + j);
                    s_remk = remk - cum;
                    s_neq  = hh[j];
                }
                cum += hh[j];
            }
        }
    };

    binsearch(KSEL);
    __syncthreads();

    bool ovf = false;
    #pragma unroll
    for (int w = 0; w < NW; ++w) ovf |= (s_cnt[w] > WCAP);
    const bool fast = !ovf && (s_tot >= KSEL) && (s_neq <= 32);

    if (fast) {
        const uint32_t bsel = s_bin;
        const int remk = s_remk, neq = s_neq;

        // ---- compact the <=32 threshold-bin keys (scan 512 slots) ----
        #pragma unroll
        for (int i = 0; i < 2; ++i) {
            int s = tid + T * i;
            if ((s & (WCAP - 1)) < s_cnt[s >> 6] && (cbm[s] >> 12) == bsel) {
                int t = atomicAdd(&s_n2, 1);
                if (t < 32) cand[t] = cbk[s];
            }
        }
        __syncthreads();

        // ---- warp0 all-pairs rank over <=32 keys -> exact threshold ----
        if (wrp == 0) {
            uint32_t mk = (lane < neq) ? cand[lane] : 0u;
            int g = 0, eq = 1;  // eq includes self
            #pragma unroll
            for (int i = 1; i < 32; ++i) {
                uint32_t ok = __shfl_sync(0xFFFFFFFFu, mk, (lane + i) & 31);
                int ol = (lane + i) & 31;
                if (ol < neq) { g += (ok > mk); eq += (ok == mk); }
            }
            if (lane < neq && g < remk && g + eq >= remk) {
                s_thr   = mk;
                s_remk2 = remk - g;
                s_allt  = (eq == remk - g);
            }
        }
        __syncthreads();
        const uint32_t thr = s_thr;
        const bool allt = (s_allt != 0);
        const int remk2 = s_remk2;

        // ---- scatter winners over the pre-written zeros ----
        #pragma unroll
        for (int i = 0; i < 2; ++i) {
            int s = tid + T * i;
            if ((s & (WCAP - 1)) < s_cnt[s >> 6]) {
                uint32_t kk = cbk[s];
                if (kk >= thr) {
                    bool inc = allt || (kk > thr);
                    if (!inc) {  // tie at thr: lowest indices first (~never)
                        uint32_t myi = cbm[s] & 0xFFFu;
                        int rk = 0;
                        for (int q = 0; q < NW * WCAP; ++q) {
                            if ((q & (WCAP - 1)) < s_cnt[q >> 6] &&
                                cbk[q] == thr && (cbm[q] & 0xFFFu) < myi)
                                rk++;
                        }
                        inc = (rk < remk2);
                    }
                    if (inc)
                        out[(size_t)row * D + (cbm[s] & 0xFFFu)] = sigm(k2f(kk));
                }
            }
        }
        return;
    }

    // ---- slow exact path (block-uniform, ~never): 8-bit radix over x ----
    {
        uint32_t prefix = 0;
        int shift = 32, remk = KSEL, neq = 0;
        while (true) {
            int w  = (shift < 8) ? shift : 8;
            int ns = shift - w;
            __syncthreads();
            hist[tid] = 0;
            __syncthreads();
            #pragma unroll
            for (int j = 0; j < 4; ++j) {
                uint4 u = x4[tid + T * j];
                #pragma unroll
                for (int e = 0; e < 4; ++e) {
                    uint32_t kk = f2k((e == 0) ? u.x : (e == 1) ? u.y
                                     : (e == 2) ? u.z : u.w);
                    bool m = (shift == 32) || ((kk >> shift) == prefix);
                    if (m) atomicAdd(&hist[(kk >> ns) & ((1u << w) - 1u)], 1);
                }
            }
            __syncthreads();
            binsearch(remk);
            __syncthreads();
            prefix = (prefix << w) | s_bin;
            remk = s_remk;
            neq  = s_neq;
            shift = ns;
            if (neq == remk || shift == 0) break;
        }
        uint32_t thr;
        bool allt;
        int remk2 = remk;
        if (neq == remk) { thr = prefix << shift; allt = true; }
        else             { thr = prefix;          allt = false; }

        #pragma unroll
        for (int j = 0; j < 4; ++j) {
            int v4 = tid + T * j;
            uint4 u = x4[v4];
            float4 r;
            #pragma unroll
            for (int e = 0; e < 4; ++e) {
                uint32_t ub = (e == 0) ? u.x : (e == 1) ? u.y
                            : (e == 2) ? u.z : u.w;
                uint32_t kk = f2k(ub);
                float o = 0.f;
                if (kk >= thr) {
                    bool inc = allt || (kk > thr);
                    if (!inc) {  // index tie-break via global scan (exact)
                        int idx = 4 * v4 + e, rk = 0;
                        const float* xr = x + (size_t)row * D;
                        for (int q = 0; q < idx; ++q)
                            rk += (f2k(__float_as_uint(xr[q])) == thr);
                        inc = (rk < remk2);
                    }
                    if (inc) o = sigm(k2f(kk));
                }
                ((float*)&r)[e] = o;
            }
            o4[v4] = r;
        }
    }
}

extern "C" void kernel_launch(void* const* d_in, const int* in_sizes, int n_in,
                              void* d_out, int out_size) {
    const float* x = (const float*)d_in[0];
    float* out = (float*)d_out;
    int rows = in_sizes[0] / D;
    topk_sigmoid_kernel<<<rows, T>>>(x, out);
}

// round 11
// speedup vs baseline: 2.5382x; 1.0660x over previous
#include <cuda_runtime.h>
#include <cuda_bf16.h>
#include <cstdint>

// TopK(k=64) + sigmoid over rows of [16384, 4096] fp32. One 256-thread CTA/row.
// Load loop: LDG row, STG zeros, push candidates (v >= 2.0, ~93/row, top-64
// superset with P_fail ~1e-3/row) into per-warp smem buffers with BALLOT
// tickets (no atomics) + 256-bin VALUE hist (bin=(v-2)*128, spread atomics).
// Buffers total 256 slots = 1 slot/thread -> single-op compaction & scatter.
// Warp0 bin search + all-pairs rank-32 give the exact threshold; winners
// scatter-overwrite their zeros. Anomalies (tail<64, warp overflow, >32 ties
// in threshold bin) -> block-uniform exact radix slow path over global x.

constexpr int D    = 4096;
constexpr int T    = 256;
constexpr int KSEL = 64;
constexpr int NB   = 256;    // value bins over [2.0, 4.0], clamp above
constexpr int NW   = 8;      // warps per CTA
constexpr int WCAP = 32;     // per-warp candidate capacity (NW*WCAP == T)

__device__ __forceinline__ uint32_t f2k(uint32_t u) {
    return u ^ ((uint32_t)((int)u >> 31) | 0x80000000u);  // monotonic key
}
__device__ __forceinline__ float k2f(uint32_t k) {
    uint32_t m = (uint32_t)((int)k >> 31);
    return __uint_as_float(k ^ (~m | 0x80000000u));
}
__device__ __forceinline__ float sigm(float f) {
    return __frcp_rn(1.0f + __expf(-f));
}
__device__ __forceinline__ int vbin(float v) {
    // monotone; v>=2.0 -> bin>=0; clamp to NB-1 (FFMA + F2I + IMNMX)
    return min(__float2int_rd(__fmaf_rz(v, 128.0f, -256.0f)), NB - 1);
}

__global__ __launch_bounds__(T, 8)
void topk_sigmoid_kernel(const float* __restrict__ x,
                         float* __restrict__ out) {
    __shared__ __align__(16) int hist[NB];
    __shared__ __align__(16) uint32_t cbk[NW * WCAP];  // candidate keys
    __shared__ __align__(16) uint32_t cbm[NW * WCAP];  // (bin<<12) | idx
    __shared__ int s_cnt[NW];
    __shared__ uint32_t cand[32];
    __shared__ uint32_t s_bin, s_thr;
    __shared__ int s_remk, s_neq, s_tot, s_n2, s_allt, s_remk2;

    const int row  = blockIdx.x;
    const int tid  = threadIdx.x;
    const int lane = tid & 31;
    const int wrp  = tid >> 5;
    const uint4* __restrict__ x4 =
        reinterpret_cast<const uint4*>(x) + (size_t)row * (D / 4);
    float4* __restrict__ o4 =
        reinterpret_cast<float4*>(out) + (size_t)row * (D / 4);

    hist[tid] = 0;                       // NB == T
    if (tid == 0) { s_n2 = 0; s_tot = 0; s_neq = 1 << 30; }
    __syncthreads();

    // ---- load + zero-out + ballot-ticket candidate push ----
    uint32_t wbase = 0;                  // per-warp slot cursor (register)
    const uint32_t ltmask = (1u << lane) - 1u;
    #pragma unroll
    for (int j = 0; j < 4; ++j) {
        int v4 = tid + T * j;
        uint4 u = x4[v4];
        o4[v4] = make_float4(0.f, 0.f, 0.f, 0.f);
        #pragma unroll
        for (int e = 0; e < 4; ++e) {
            uint32_t ub = (e == 0) ? u.x : (e == 1) ? u.y : (e == 2) ? u.z : u.w;
            float vv = __uint_as_float(ub);
            bool c = (vv >= 2.0f);                   // ~93/4096 per row
            unsigned act = __ballot_sync(0xFFFFFFFFu, c);
            if (c) {
                int b = vbin(vv);
                atomicAdd(&hist[b], 1);              // spread: <1 key/bin
                uint32_t slot = wbase + __popc(act & ltmask);
                if (slot < WCAP) {
                    cbk[wrp * WCAP + slot] = f2k(ub);
                    cbm[wrp * WCAP + slot] =
                        ((uint32_t)b << 12) | (uint32_t)(4 * v4 + e);
                }
            }
            wbase += __popc(act);
        }
    }
    if (lane == 0) s_cnt[wrp] = (int)wbase;
    __syncthreads();

    // ---- warp0-only bin search over hist[256]; lane owns 8 bins ----
    auto binsearch = [&](int remk) {
        if (wrp == 0) {
            int4 qa = reinterpret_cast<const int4*>(hist)[lane * 2];
            int4 qb = reinterpret_cast<const int4*>(hist)[lane * 2 + 1];
            int tot = qa.x + qa.y + qa.z + qa.w + qb.x + qb.y + qb.z + qb.w;
            int s = tot;  // inclusive suffix over lanes >= mine
            #pragma unroll
            for (int o = 1; o < 32; o <<= 1) {
                int q = __shfl_down_sync(0xFFFFFFFFu, s, o);
                if (lane + o < 32) s += q;
            }
            if (lane == 0) s_tot = s;
            int cum = s - tot;  // count in bins strictly above my 8
            int hh[8] = {qa.x, qa.y, qa.z, qa.w, qb.x, qb.y, qb.z, qb.w};
            #pragma unroll
            for (int j = 7; j >= 0; --j) {
                if (cum < remk && cum + hh[j] >= remk) {  // unique hit
                    s_bin  = (uint32_t)(lane * 8 + j);
                    s_remk = remk - cum;
                    s_neq  = hh[j];
                }
                cum += hh[j];
            }
        }
    };

    binsearch(KSEL);
    __syncthreads();

    bool ovf = false;
    #pragma unroll
    for (int w = 0; w < NW; ++w) ovf |= (s_cnt[w] > WCAP);
    const bool fast = !ovf && (s_tot >= KSEL) && (s_neq <= 32);

    if (fast) {
        const uint32_t bsel = s_bin;
        const int remk = s_remk, neq = s_neq;

        // ---- compact threshold-bin keys: exactly 1 slot per thread ----
        const bool mine = (lane < s_cnt[wrp]);
        const uint32_t mym = cbm[tid];
        const uint32_t myk = cbk[tid];
        if (mine && (mym >> 12) == bsel) {
            int t = atomicAdd(&s_n2, 1);             // ~1-2 pushes per row
            if (t < 32) cand[t] = myk;
        }
        __syncthreads();

        // ---- warp0 all-pairs rank over <=32 keys -> exact threshold ----
        if (wrp == 0) {
            uint32_t mk = (lane < neq) ? cand[lane] : 0u;
            int g = 0, eq = 1;  // eq includes self
            #pragma unroll
            for (int i = 1; i < 32; ++i) {
                uint32_t ok = __shfl_sync(0xFFFFFFFFu, mk, (lane + i) & 31);
                int ol = (lane + i) & 31;
                if (ol < neq) { g += (ok > mk); eq += (ok == mk); }
            }
            if (lane < neq && g < remk && g + eq >= remk) {
                s_thr   = mk;
                s_remk2 = remk - g;
                s_allt  = (eq == remk - g);
            }
        }
        __syncthreads();
        const uint32_t thr = s_thr;
        const bool allt = (s_allt != 0);
        const int remk2 = s_remk2;

        // ---- scatter winners over the pre-written zeros (1 slot/thread) ----
        if (mine && myk >= thr) {
            bool inc = allt || (myk > thr);
            if (!inc) {  // tie at thr: lowest indices first (~never)
                uint32_t myi = mym & 0xFFFu;
                int rk = 0;
                for (int q = 0; q < NW * WCAP; ++q) {
                    if ((q & (WCAP - 1)) < s_cnt[q >> 5] &&
                        cbk[q] == thr && (cbm[q] & 0xFFFu) < myi)
                        rk++;
                }
                inc = (rk < remk2);
            }
            if (inc)
                out[(size_t)row * D + (mym & 0xFFFu)] = sigm(k2f(myk));
        }
        return;
    }

    // ---- slow exact path (block-uniform, rare): 8-bit radix over x ----
    {
        uint32_t prefix = 0;
        int shift = 32, remk = KSEL, neq = 0;
        while (true) {
            int w  = (shift < 8) ? shift : 8;
            int ns = shift - w;
            __syncthreads();
            hist[tid] = 0;
            __syncthreads();
            #pragma unroll
            for (int j = 0; j < 4; ++j) {
                uint4 u = x4[tid + T * j];
                #pragma unroll
                for (int e = 0; e < 4; ++e) {
                    uint32_t kk = f2k((e == 0) ? u.x : (e == 1) ? u.y
                                     : (e == 2) ? u.z : u.w);
                    bool m = (shift == 32) || ((kk >> shift) == prefix);
                    if (m) atomicAdd(&hist[(kk >> ns) & ((1u << w) - 1u)], 1);
                }
            }
            __syncthreads();
            binsearch(remk);
            __syncthreads();
            prefix = (prefix << w) | s_bin;
            remk = s_remk;
            neq  = s_neq;
            shift = ns;
            if (neq == remk || shift == 0) break;
        }
        uint32_t thr;
        bool allt;
        int remk2 = remk;
        if (neq == remk) { thr = prefix << shift; allt = true; }
        else             { thr = prefix;          allt = false; }

        #pragma unroll
        for (int j = 0; j < 4; ++j) {
            int v4 = tid + T * j;
            uint4 u = x4[v4];
            float4 r;
            #pragma unroll
            for (int e = 0; e < 4; ++e) {
                uint32_t ub = (e == 0) ? u.x : (e == 1) ? u.y
                            : (e == 2) ? u.z : u.w;
                uint32_t kk = f2k(ub);
                float o = 0.f;
                if (kk >= thr) {
                    bool inc = allt || (kk > thr);
                    if (!inc) {  // index tie-break via global scan (exact)
                        int idx = 4 * v4 + e, rk = 0;
                        const float* xr = x + (size_t)row * D;
                        for (int q = 0; q < idx; ++q)
                            rk += (f2k(__float_as_uint(xr[q])) == thr);
                        inc = (rk < remk2);
                    }
                    if (inc) o = sigm(k2f(kk));
                }
                ((float*)&r)[e] = o;
            }
            o4[v4] = r;
        }
    }
}

extern "C" void kernel_launch(void* const* d_in, const int* in_sizes, int n_in,
                              void* d_out, int out_size) {
    const float* x = (const float*)d_in[0];
    float* out = (float*)d_out;
    int rows = in_sizes[0] / D;
    topk_sigmoid_kernel<<<rows, T>>>(x, out);
}

// round 12
// speedup vs baseline: 2.7038x; 1.0652x over previous
#include <cuda_runtime.h>
#include <cuda_bf16.h>
#include <cstdint>

// TopK(k=64) + sigmoid over rows of [16384, 4096] fp32. One 256-thread CTA/row.
// Load loop: LDG row, STG zeros, candidates (v >= 2.0, ~93/row, top-64
// superset with P_fail ~1e-3/row) take a per-warp atomic ticket (~12/warp,
// cheaper than 16 ballots now that candidates are this rare) into per-warp
// smem buffers + 256-bin VALUE hist (bin=(v-2)*128, spread). Fast path works
// on RAW positive-float bits (monotone for positives — no key transform).
// Warp0 bin search + all-pairs rank-32 give the exact threshold; winners
// scatter-overwrite their zeros. Anomalies (tail<64, warp overflow, >32 ties
// in threshold bin) -> block-uniform exact radix slow path over global x.

constexpr int D    = 4096;
constexpr int T    = 256;
constexpr int KSEL = 64;
constexpr int NB   = 256;    // value bins over [2.0, 4.0], clamp above
constexpr int NW   = 8;      // warps per CTA
constexpr int WCAP = 32;     // per-warp candidate capacity (NW*WCAP == T)

__device__ __forceinline__ uint32_t f2k(uint32_t u) {
    return u ^ ((uint32_t)((int)u >> 31) | 0x80000000u);  // monotonic key
}
__device__ __forceinline__ float k2f(uint32_t k) {
    uint32_t m = (uint32_t)((int)k >> 31);
    return __uint_as_float(k ^ (~m | 0x80000000u));
}
__device__ __forceinline__ float sigm(float f) {
    return __frcp_rn(1.0f + __expf(-f));
}
__device__ __forceinline__ int vbin(float v) {
    // monotone; v>=2.0 -> bin>=0; clamp to NB-1 (FFMA + F2I + IMNMX)
    return min(__float2int_rd(__fmaf_rz(v, 128.0f, -256.0f)), NB - 1);
}

__global__ __launch_bounds__(T, 8)
void topk_sigmoid_kernel(const float* __restrict__ x,
                         float* __restrict__ out) {
    __shared__ __align__(16) int hist[NB];
    __shared__ __align__(16) uint32_t cbk[NW * WCAP];  // raw float bits
    __shared__ __align__(16) uint32_t cbm[NW * WCAP];  // (bin<<12) | idx
    __shared__ int s_cnt[NW];
    __shared__ uint32_t cand[32];
    __shared__ uint32_t s_bin, s_thr;
    __shared__ int s_remk, s_neq, s_tot, s_n2, s_allt, s_remk2;

    const int row  = blockIdx.x;
    const int tid  = threadIdx.x;
    const int lane = tid & 31;
    const int wrp  = tid >> 5;
    const uint4* __restrict__ x4 =
        reinterpret_cast<const uint4*>(x) + (size_t)row * (D / 4);
    float4* __restrict__ o4 =
        reinterpret_cast<float4*>(out) + (size_t)row * (D / 4);

    hist[tid] = 0;                       // NB == T
    if (tid < NW) s_cnt[tid] = 0;
    if (tid == 0) { s_n2 = 0; s_tot = 0; s_neq = 1 << 30; }
    __syncthreads();

    // ---- load + zero-out + rare atomic-ticket candidate push ----
    #pragma unroll
    for (int j = 0; j < 4; ++j) {
        int v4 = tid + T * j;
        uint4 u = x4[v4];
        o4[v4] = make_float4(0.f, 0.f, 0.f, 0.f);
        #pragma unroll
        for (int e = 0; e < 4; ++e) {
            uint32_t ub = (e == 0) ? u.x : (e == 1) ? u.y : (e == 2) ? u.z : u.w;
            float vv = __uint_as_float(ub);
            if (vv >= 2.0f) {                        // ~93/4096 per row
                int b = vbin(vv);
                atomicAdd(&hist[b], 1);              // spread: <1 key/bin
                int slot = atomicAdd(&s_cnt[wrp], 1);  // ~12/warp total
                if (slot < WCAP) {
                    cbk[wrp * WCAP + slot] = ub;     // raw bits (positive)
                    cbm[wrp * WCAP + slot] =
                        ((uint32_t)b << 12) | (uint32_t)(4 * v4 + e);
                }
            }
        }
    }
    __syncthreads();

    // ---- warp0-only bin search over hist[256]; lane owns 8 bins ----
    auto binsearch = [&](int remk) {
        if (wrp == 0) {
            int4 qa = reinterpret_cast<const int4*>(hist)[lane * 2];
            int4 qb = reinterpret_cast<const int4*>(hist)[lane * 2 + 1];
            int tot = qa.x + qa.y + qa.z + qa.w + qb.x + qb.y + qb.z + qb.w;
            int s = tot;  // inclusive suffix over lanes >= mine
            #pragma unroll
            for (int o = 1; o < 32; o <<= 1) {
                int q = __shfl_down_sync(0xFFFFFFFFu, s, o);
                if (lane + o < 32) s += q;
            }
            if (lane == 0) s_tot = s;
            int cum = s - tot;  // count in bins strictly above my 8
            int hh[8] = {qa.x, qa.y, qa.z, qa.w, qb.x, qb.y, qb.z, qb.w};
            #pragma unroll
            for (int j = 7; j >= 0; --j) {
                if (cum < remk && cum + hh[j] >= remk) {  // unique hit
                    s_bin  = (uint32_t)(lane * 8 + j);
                    s_remk = remk - cum;
                    s_neq  = hh[j];
                }
                cum += hh[j];
            }
        }
    };

    binsearch(KSEL);
    __syncthreads();

    bool ovf = false;
    #pragma unroll
    for (int w = 0; w < NW; ++w) ovf |= (s_cnt[w] > WCAP);
    const bool fast = !ovf && (s_tot >= KSEL) && (s_neq <= 32);

    if (fast) {
        const uint32_t bsel = s_bin;
        const int remk = s_remk, neq = s_neq;

        // ---- compact threshold-bin keys: exactly 1 slot per thread ----
        const bool mine = (lane < s_cnt[wrp]);
        const uint32_t mym = cbm[tid];
        const uint32_t myk = cbk[tid];
        if (mine && (mym >> 12) == bsel) {
            int t = atomicAdd(&s_n2, 1);             // ~1-2 pushes per row
            if (t < 32) cand[t] = myk;
        }
        __syncthreads();

        // ---- warp0 all-pairs rank over <=32 keys -> exact threshold ----
        // raw bits of positive floats compare correctly as uint
        if (wrp == 0) {
            uint32_t mk = (lane < neq) ? cand[lane] : 0u;
            int g = 0, eq = 1;  // eq includes self
            #pragma unroll
            for (int i = 1; i < 32; ++i) {
                uint32_t ok = __shfl_sync(0xFFFFFFFFu, mk, (lane + i) & 31);
                int ol = (lane + i) & 31;
                if (ol < neq) { g += (ok > mk); eq += (ok == mk); }
            }
            if (lane < neq && g < remk && g + eq >= remk) {
                s_thr   = mk;
                s_remk2 = remk - g;
                s_allt  = (eq == remk - g);
            }
        }
        __syncthreads();
        const uint32_t thr = s_thr;
        const bool allt = (s_allt != 0);
        const int remk2 = s_remk2;

        // ---- scatter winners over the pre-written zeros (1 slot/thread) ----
        if (mine && myk >= thr) {
            bool inc = allt || (myk > thr);
            if (!inc) {  // tie at thr: lowest indices first (~never)
                uint32_t myi = mym & 0xFFFu;
                int rk = 0;
                for (int q = 0; q < NW * WCAP; ++q) {
                    if ((q & (WCAP - 1)) < s_cnt[q >> 5] &&
                        cbk[q] == thr && (cbm[q] & 0xFFFu) < myi)
                        rk++;
                }
                inc = (rk < remk2);
            }
            if (inc)
                out[(size_t)row * D + (mym & 0xFFFu)] =
                    sigm(__uint_as_float(myk));
        }
        return;
    }

    // ---- slow exact path (block-uniform, rare): 8-bit radix over x ----
    {
        uint32_t prefix = 0;
        int shift = 32, remk = KSEL, neq = 0;
        while (true) {
            int w  = (shift < 8) ? shift : 8;
            int ns = shift - w;
            __syncthreads();
            hist[tid] = 0;
            __syncthreads();
            #pragma unroll
            for (int j = 0; j < 4; ++j) {
                uint4 u = x4[tid + T * j];
                #pragma unroll
                for (int e = 0; e < 4; ++e) {
                    uint32_t kk = f2k((e == 0) ? u.x : (e == 1) ? u.y
                                     : (e == 2) ? u.z : u.w);
                    bool m = (shift == 32) || ((kk >> shift) == prefix);
                    if (m) atomicAdd(&hist[(kk >> ns) & ((1u << w) - 1u)], 1);
                }
            }
            __syncthreads();
            binsearch(remk);
            __syncthreads();
            prefix = (prefix << w) | s_bin;
            remk = s_remk;
            neq  = s_neq;
            shift = ns;
            if (neq == remk || shift == 0) break;
        }
        uint32_t thr;
        bool allt;
        int remk2 = remk;
        if (neq == remk) { thr = prefix << shift; allt = true; }
        else             { thr = prefix;          allt = false; }

        #pragma unroll
        for (int j = 0; j < 4; ++j) {
            int v4 = tid + T * j;
            uint4 u = x4[v4];
            float4 r;
            #pragma unroll
            for (int e = 0; e < 4; ++e) {
                uint32_t ub = (e == 0) ? u.x : (e == 1) ? u.y
                            : (e == 2) ? u.z : u.w;
                uint32_t kk = f2k(ub);
                float o = 0.f;
                if (kk >= thr) {
                    bool inc = allt || (kk > thr);
                    if (!inc) {  // index tie-break via global scan (exact)
                        int idx = 4 * v4 + e, rk = 0;
                        const float* xr = x + (size_t)row * D;
                        for (int q = 0; q < idx; ++q)
                            rk += (f2k(__float_as_uint(xr[q])) == thr);
                        inc = (rk < remk2);
                    }
                    if (inc) o = sigm(k2f(kk));
                }
                ((float*)&r)[e] = o;
            }
            o4[v4] = r;
        }
    }
}

extern "C" void kernel_launch(void* const* d_in, const int* in_sizes, int n_in,
                              void* d_out, int out_size) {
    const float* x = (const float*)d_in[0];
    float* out = (float*)d_out;
    int rows = in_sizes[0] / D;
    topk_sigmoid_kernel<<<rows, T>>>(x, out);
}

// round 13
// speedup vs baseline: 2.7892x; 1.0316x over previous
#include <cuda_runtime.h>
#include <cuda_bf16.h>
#include <cstdint>

// TopK(k=64) + sigmoid over rows of [16384, 4096] fp32. One 256-thread CTA/row.
// Load loop: 4 front-batched LDG.128 (MLP=4), 4 STG.128 zeros, then a
// per-quad FMNMX group test (max(quad) >= 2.0, ~8.8% taken) guarding the
// per-element candidate path (v >= 2.0, ~93/row, top-64 superset with
// P_fail ~1e-3/row). Candidates take a per-warp atomic ticket into smem
// buffers + a 256-bin VALUE hist (bin=(v-2)*128, spread). Fast path works on
// RAW positive-float bits (monotone for positives). Warp0 bin search +
// all-pairs rank-32 give the exact threshold; winners scatter-overwrite
// their zeros. Anomalies (tail<64, warp overflow, >32 ties in threshold
// bin) -> block-uniform exact radix slow path over global x.

constexpr int D    = 4096;
constexpr int T    = 256;
constexpr int KSEL = 64;
constexpr int NB   = 256;    // value bins over [2.0, 4.0], clamp above
constexpr int NW   = 8;      // warps per CTA
constexpr int WCAP = 32;     // per-warp candidate capacity (NW*WCAP == T)

__device__ __forceinline__ uint32_t f2k(uint32_t u) {
    return u ^ ((uint32_t)((int)u >> 31) | 0x80000000u);  // monotonic key
}
__device__ __forceinline__ float k2f(uint32_t k) {
    uint32_t m = (uint32_t)((int)k >> 31);
    return __uint_as_float(k ^ (~m | 0x80000000u));
}
__device__ __forceinline__ float sigm(float f) {
    return __frcp_rn(1.0f + __expf(-f));
}
__device__ __forceinline__ int vbin(float v) {
    // monotone; v>=2.0 -> bin>=0; clamp to NB-1 (FFMA + F2I + IMNMX)
    return min(__float2int_rd(__fmaf_rz(v, 128.0f, -256.0f)), NB - 1);
}

__global__ __launch_bounds__(T, 8)
void topk_sigmoid_kernel(const float* __restrict__ x,
                         float* __restrict__ out) {
    __shared__ __align__(16) int hist[NB];
    __shared__ __align__(16) uint32_t cbk[NW * WCAP];  // raw float bits
    __shared__ __align__(16) uint32_t cbm[NW * WCAP];  // (bin<<12) | idx
    __shared__ int s_cnt[NW];
    __shared__ uint32_t cand[32];
    __shared__ uint32_t s_bin, s_thr;
    __shared__ int s_remk, s_neq, s_tot, s_n2, s_allt, s_remk2;

    const int row  = blockIdx.x;
    const int tid  = threadIdx.x;
    const int lane = tid & 31;
    const int wrp  = tid >> 5;
    const uint4* __restrict__ x4 =
        reinterpret_cast<const uint4*>(x) + (size_t)row * (D / 4);
    float4* __restrict__ o4 =
        reinterpret_cast<float4*>(out) + (size_t)row * (D / 4);

    hist[tid] = 0;                       // NB == T
    if (tid < NW) s_cnt[tid] = 0;
    if (tid == 0) { s_n2 = 0; s_tot = 0; s_neq = 1 << 30; }
    __syncthreads();

    // ---- 4 front-batched LDG.128 (MLP=4), then 4 STG.128 zeros ----
    uint4 u[4];
    #pragma unroll
    for (int j = 0; j < 4; ++j) u[j] = x4[tid + T * j];
    const float4 z4 = make_float4(0.f, 0.f, 0.f, 0.f);
    #pragma unroll
    for (int j = 0; j < 4; ++j) o4[tid + T * j] = z4;

    // ---- per-quad group test, rare per-element candidate path ----
    #pragma unroll
    for (int j = 0; j < 4; ++j) {
        const float fx = __uint_as_float(u[j].x);
        const float fy = __uint_as_float(u[j].y);
        const float fz = __uint_as_float(u[j].z);
        const float fw = __uint_as_float(u[j].w);
        const float mx = fmaxf(fmaxf(fx, fy), fmaxf(fz, fw));
        if (mx >= 2.0f) {                            // ~8.8% of quads
            #pragma unroll
            for (int e = 0; e < 4; ++e) {
                uint32_t ub = (e == 0) ? u[j].x : (e == 1) ? u[j].y
                            : (e == 2) ? u[j].z : u[j].w;
                float vv = __uint_as_float(ub);
                if (vv >= 2.0f) {                    // ~93/4096 per row
                    int b = vbin(vv);
                    atomicAdd(&hist[b], 1);          // spread: <1 key/bin
                    int slot = atomicAdd(&s_cnt[wrp], 1);  // ~12/warp
                    if (slot < WCAP) {
                        cbk[wrp * WCAP + slot] = ub; // raw bits (positive)
                        cbm[wrp * WCAP + slot] =
                            ((uint32_t)b << 12) |
                            (uint32_t)(4 * (tid + T * j) + e);
                    }
                }
            }
        }
    }
    __syncthreads();

    // ---- warp0-only bin search over hist[256]; lane owns 8 bins ----
    auto binsearch = [&](int remk) {
        if (wrp == 0) {
            int4 qa = reinterpret_cast<const int4*>(hist)[lane * 2];
            int4 qb = reinterpret_cast<const int4*>(hist)[lane * 2 + 1];
            int tot = qa.x + qa.y + qa.z + qa.w + qb.x + qb.y + qb.z + qb.w;
            int s = tot;  // inclusive suffix over lanes >= mine
            #pragma unroll
            for (int o = 1; o < 32; o <<= 1) {
                int q = __shfl_down_sync(0xFFFFFFFFu, s, o);
                if (lane + o < 32) s += q;
            }
            if (lane == 0) s_tot = s;
            int cum = s - tot;  // count in bins strictly above my 8
            int hh[8] = {qa.x, qa.y, qa.z, qa.w, qb.x, qb.y, qb.z, qb.w};
            #pragma unroll
            for (int j = 7; j >= 0; --j) {
                if (cum < remk && cum + hh[j] >= remk) {  // unique hit
                    s_bin  = (uint32_t)(lane * 8 + j);
                    s_remk = remk - cum;
                    s_neq  = hh[j];
                }
                cum += hh[j];
            }
        }
    };

    binsearch(KSEL);
    __syncthreads();

    bool ovf = false;
    #pragma unroll
    for (int w = 0; w < NW; ++w) ovf |= (s_cnt[w] > WCAP);
    const bool fast = !ovf && (s_tot >= KSEL) && (s_neq <= 32);

    if (fast) {
        const uint32_t bsel = s_bin;
        const int remk = s_remk, neq = s_neq;

        // ---- compact threshold-bin keys: exactly 1 slot per thread ----
        const bool mine = (lane < s_cnt[wrp]);
        const uint32_t mym = cbm[tid];
        const uint32_t myk = cbk[tid];
        if (mine && (mym >> 12) == bsel) {
            int t = atomicAdd(&s_n2, 1);             // ~1-2 pushes per row
            if (t < 32) cand[t] = myk;
        }
        __syncthreads();

        // ---- warp0 all-pairs rank over <=32 keys -> exact threshold ----
        if (wrp == 0) {
            uint32_t mk = (lane < neq) ? cand[lane] : 0u;
            int g = 0, eq = 1;  // eq includes self
            #pragma unroll
            for (int i = 1; i < 32; ++i) {
                uint32_t ok = __shfl_sync(0xFFFFFFFFu, mk, (lane + i) & 31);
                int ol = (lane + i) & 31;
                if (ol < neq) { g += (ok > mk); eq += (ok == mk); }
            }
            if (lane < neq && g < remk && g + eq >= remk) {
                s_thr   = mk;
                s_remk2 = remk - g;
                s_allt  = (eq == remk - g);
            }
        }
        __syncthreads();
        const uint32_t thr = s_thr;
        const bool allt = (s_allt != 0);
        const int remk2 = s_remk2;

        // ---- scatter winners over the pre-written zeros (1 slot/thread) ----
        if (mine && myk >= thr) {
            bool inc = allt || (myk > thr);
            if (!inc) {  // tie at thr: lowest indices first (~never)
                uint32_t myi = mym & 0xFFFu;
                int rk = 0;
                for (int q = 0; q < NW * WCAP; ++q) {
                    if ((q & (WCAP - 1)) < s_cnt[q >> 5] &&
                        cbk[q] == thr && (cbm[q] & 0xFFFu) < myi)
                        rk++;
                }
                inc = (rk < remk2);
            }
            if (inc)
                out[(size_t)row * D + (mym & 0xFFFu)] =
                    sigm(__uint_as_float(myk));
        }
        return;
    }

    // ---- slow exact path (block-uniform, rare): 8-bit radix over x ----
    {
        uint32_t prefix = 0;
        int shift = 32, remk = KSEL, neq = 0;
        while (true) {
            int w  = (shift < 8) ? shift : 8;
            int ns = shift - w;
            __syncthreads();
            hist[tid] = 0;
            __syncthreads();
            #pragma unroll
            for (int j = 0; j < 4; ++j) {
                #pragma unroll
                for (int e = 0; e < 4; ++e) {
                    uint32_t kk = f2k((e == 0) ? u[j].x : (e == 1) ? u[j].y
                                     : (e == 2) ? u[j].z : u[j].w);
                    bool m = (shift == 32) || ((kk >> shift) == prefix);
                    if (m) atomicAdd(&hist[(kk >> ns) & ((1u << w) - 1u)], 1);
                }
            }
            __syncthreads();
            binsearch(remk);
            __syncthreads();
            prefix = (prefix << w) | s_bin;
            remk = s_remk;
            neq  = s_neq;
            shift = ns;
            if (neq == remk || shift == 0) break;
        }
        uint32_t thr;
        bool allt;
        int remk2 = remk;
        if (neq == remk) { thr = prefix << shift; allt = true; }
        else             { thr = prefix;          allt = false; }

        #pragma unroll
        for (int j = 0; j < 4; ++j) {
            int v4 = tid + T * j;
            float4 r;
            #pragma unroll
            for (int e = 0; e < 4; ++e) {
                uint32_t ub = (e == 0) ? u[j].x : (e == 1) ? u[j].y
                            : (e == 2) ? u[j].z : u[j].w;
                uint32_t kk = f2k(ub);
                float o = 0.f;
                if (kk >= thr) {
                    bool inc = allt || (kk > thr);
                    if (!inc) {  // index tie-break via global scan (exact)
                        int idx = 4 * v4 + e, rk = 0;
                        const float* xr = x + (size_t)row * D;
                        for (int q = 0; q < idx; ++q)
                            rk += (f2k(__float_as_uint(xr[q])) == thr);
                        inc = (rk < remk2);
                    }
                    if (inc) o = sigm(k2f(kk));
                }
                ((float*)&r)[e] = o;
            }
            o4[v4] = r;
        }
    }
}

extern "C" void kernel_launch(void* const* d_in, const int* in_sizes, int n_in,
                              void* d_out, int out_size) {
    const float* x = (const float*)d_in[0];
    float* out = (float*)d_out;
    int rows = in_sizes[0] / D;
    topk_sigmoid_kernel<<<rows, T>>>(x, out);
}